// round 1
// baseline (speedup 1.0000x reference)
#include <cuda_runtime.h>
#include <math.h>

#define N_TOK 8192
#define C_DIM 1024
#define D_DIM 1024
#define E_NUM 8
#define SLOTS (N_TOK * 2)

// ---- scratch (static __device__ per allocation rules) ----
__device__ int   g_counts[E_NUM];
__device__ int   g_base[E_NUM];
__device__ int   g_cursor[E_NUM];
__device__ int   g_tok_e[SLOTS];    // per-token top2 expert ids
__device__ float g_tok_p[SLOTS];    // per-token top2 probs
__device__ int   g_slot_tok[SLOTS]; // slot -> token
__device__ float g_slot_p[SLOTS];   // slot -> prob
__device__ float g_hidden[(size_t)SLOTS * D_DIM]; // 64MB hidden scratch

// ------------------------------------------------------------------
__global__ void init_kernel() {
    int t = threadIdx.x;
    if (t < E_NUM) g_counts[t] = 0;
}

// ------------------------------------------------------------------
// Router: one warp per token. logits = x @ rw^T, top-2, softmax.
__global__ void router_kernel(const float* __restrict__ x,
                              const float* __restrict__ rw) {
    __shared__ float srw[E_NUM * C_DIM]; // 32KB
    int tid = threadIdx.x;
    for (int i = tid; i < E_NUM * C_DIM; i += 256) srw[i] = rw[i];
    __syncthreads();

    int warp = tid >> 5, lane = tid & 31;
    int token = blockIdx.x * 8 + warp;
    const float* xr = x + (size_t)token * C_DIM;

    float acc[E_NUM];
#pragma unroll
    for (int e = 0; e < E_NUM; e++) acc[e] = 0.f;

    for (int c = lane; c < C_DIM; c += 32) {
        float xv = xr[c];
#pragma unroll
        for (int e = 0; e < E_NUM; e++) acc[e] += xv * srw[e * C_DIM + c];
    }
#pragma unroll
    for (int e = 0; e < E_NUM; e++) {
#pragma unroll
        for (int o = 16; o; o >>= 1)
            acc[e] += __shfl_xor_sync(0xffffffffu, acc[e], o);
    }
    if (lane == 0) {
        int e0 = 0; float v0 = acc[0];
#pragma unroll
        for (int e = 1; e < E_NUM; e++)
            if (acc[e] > v0) { v0 = acc[e]; e0 = e; }
        int e1 = -1; float v1 = -INFINITY;
#pragma unroll
        for (int e = 0; e < E_NUM; e++)
            if (e != e0 && acc[e] > v1) { v1 = acc[e]; e1 = e; }
        float t  = expf(v1 - v0);       // v1 <= v0, safe
        float p0 = 1.f / (1.f + t);
        float p1 = t / (1.f + t);
        g_tok_e[token * 2 + 0] = e0;
        g_tok_e[token * 2 + 1] = e1;
        g_tok_p[token * 2 + 0] = p0;
        g_tok_p[token * 2 + 1] = p1;
        atomicAdd(&g_counts[e0], 1);
        atomicAdd(&g_counts[e1], 1);
    }
}

// ------------------------------------------------------------------
__global__ void offsets_kernel() {
    int s = 0;
    for (int e = 0; e < E_NUM; e++) {
        g_base[e]   = s;
        g_cursor[e] = s;
        s += g_counts[e];
    }
}

__global__ void scatter_kernel() {
    int n = blockIdx.x * blockDim.x + threadIdx.x;
    if (n >= N_TOK) return;
#pragma unroll
    for (int k = 0; k < 2; k++) {
        int e = g_tok_e[n * 2 + k];
        int slot = atomicAdd(&g_cursor[e], 1);
        g_slot_tok[slot] = n;
        g_slot_p[slot]   = g_tok_p[n * 2 + k];
    }
}

// ------------------------------------------------------------------
// GEMM1: H[slot, :] = relu(x[token(slot), :] @ w1[e])^2
// tile 128x128, BK=16, 256 threads, 8x8 per thread
__global__ __launch_bounds__(256)
void gemm1_kernel(const float* __restrict__ x, const float* __restrict__ w1) {
    const int e  = blockIdx.z;
    const int ne = g_counts[e];
    const int m0 = blockIdx.y * 128;
    if (m0 >= ne) return;
    const int n0   = blockIdx.x * 128;
    const int base = g_base[e];

    __shared__ float As[16][128];
    __shared__ float Bs[16][128];
    __shared__ int   stok[128];

    const int tid = threadIdx.x;
    if (tid < 128) {
        int m = m0 + tid;
        stok[tid] = (m < ne) ? g_slot_tok[base + m] : -1;
    }
    __syncthreads();

    const float* B = w1 + (size_t)e * C_DIM * D_DIM + n0;

    const int tx = tid & 15, ty = tid >> 4;
    // A-load mapping: row r = tid>>1, k-offset = (tid&1)*8 (two float4)
    const int ar   = tid >> 1;
    const int aoff = (tid & 1) * 8;
    const int atok = stok[ar];
    // B-load mapping: thread handles vec idx tid and tid+256
    const int bk0 = tid >> 5;            // 0..7
    const int bn  = (tid & 31) * 4;      // 0..124

    float acc[8][8];
#pragma unroll
    for (int i = 0; i < 8; i++)
#pragma unroll
        for (int j = 0; j < 8; j++) acc[i][j] = 0.f;

    for (int k0 = 0; k0 < C_DIM; k0 += 16) {
        // global -> smem, A
        float4 va0, va1;
        if (atok >= 0) {
            const float* ap = x + (size_t)atok * C_DIM + k0 + aoff;
            va0 = *(const float4*)(ap);
            va1 = *(const float4*)(ap + 4);
        } else {
            va0 = make_float4(0.f, 0.f, 0.f, 0.f);
            va1 = va0;
        }
        As[aoff + 0][ar] = va0.x; As[aoff + 1][ar] = va0.y;
        As[aoff + 2][ar] = va0.z; As[aoff + 3][ar] = va0.w;
        As[aoff + 4][ar] = va1.x; As[aoff + 5][ar] = va1.y;
        As[aoff + 6][ar] = va1.z; As[aoff + 7][ar] = va1.w;
        // global -> smem, B (rows k0+bk0 and k0+bk0+8)
        float4 vb0 = *(const float4*)(B + (size_t)(k0 + bk0)     * D_DIM + bn);
        float4 vb1 = *(const float4*)(B + (size_t)(k0 + bk0 + 8) * D_DIM + bn);
        *(float4*)&Bs[bk0][bn]     = vb0;
        *(float4*)&Bs[bk0 + 8][bn] = vb1;
        __syncthreads();

#pragma unroll
        for (int kk = 0; kk < 16; kk++) {
            float4 a0 = *(float4*)&As[kk][ty * 8];
            float4 a1 = *(float4*)&As[kk][ty * 8 + 4];
            float4 b0 = *(float4*)&Bs[kk][tx * 8];
            float4 b1 = *(float4*)&Bs[kk][tx * 8 + 4];
            float a[8] = {a0.x, a0.y, a0.z, a0.w, a1.x, a1.y, a1.z, a1.w};
            float b[8] = {b0.x, b0.y, b0.z, b0.w, b1.x, b1.y, b1.z, b1.w};
#pragma unroll
            for (int i = 0; i < 8; i++)
#pragma unroll
                for (int j = 0; j < 8; j++) acc[i][j] += a[i] * b[j];
        }
        __syncthreads();
    }

    // epilogue: relu^2, store to hidden
#pragma unroll
    for (int i = 0; i < 8; i++) {
        int m = m0 + ty * 8 + i;
        if (m >= ne) break;
        float* hp = g_hidden + (size_t)(base + m) * D_DIM + n0 + tx * 8;
        float4 o0, o1;
        float r;
        r = fmaxf(acc[i][0], 0.f); o0.x = r * r;
        r = fmaxf(acc[i][1], 0.f); o0.y = r * r;
        r = fmaxf(acc[i][2], 0.f); o0.z = r * r;
        r = fmaxf(acc[i][3], 0.f); o0.w = r * r;
        r = fmaxf(acc[i][4], 0.f); o1.x = r * r;
        r = fmaxf(acc[i][5], 0.f); o1.y = r * r;
        r = fmaxf(acc[i][6], 0.f); o1.z = r * r;
        r = fmaxf(acc[i][7], 0.f); o1.w = r * r;
        *(float4*)(hp)     = o0;
        *(float4*)(hp + 4) = o1;
    }
}

// ------------------------------------------------------------------
// GEMM2: out[token, :] += prob * (H[slot, :] @ w2[e])
__global__ __launch_bounds__(256)
void gemm2_kernel(const float* __restrict__ w2, float* __restrict__ out) {
    const int e  = blockIdx.z;
    const int ne = g_counts[e];
    const int m0 = blockIdx.y * 128;
    if (m0 >= ne) return;
    const int n0   = blockIdx.x * 128;
    const int base = g_base[e];

    __shared__ float As[16][128];
    __shared__ float Bs[16][128];
    __shared__ int   stok[128];
    __shared__ float sp[128];

    const int tid = threadIdx.x;
    if (tid < 128) {
        int m = m0 + tid;
        if (m < ne) {
            stok[tid] = g_slot_tok[base + m];
            sp[tid]   = g_slot_p[base + m];
        } else {
            stok[tid] = -1;
            sp[tid]   = 0.f;
        }
    }
    __syncthreads();

    const float* B = w2 + (size_t)e * D_DIM * C_DIM + n0;

    const int tx = tid & 15, ty = tid >> 4;
    const int ar   = tid >> 1;
    const int aoff = (tid & 1) * 8;
    const bool avalid = (m0 + ar) < ne;
    const int bk0 = tid >> 5;
    const int bn  = (tid & 31) * 4;

    float acc[8][8];
#pragma unroll
    for (int i = 0; i < 8; i++)
#pragma unroll
        for (int j = 0; j < 8; j++) acc[i][j] = 0.f;

    for (int k0 = 0; k0 < D_DIM; k0 += 16) {
        float4 va0, va1;
        if (avalid) {
            const float* ap = g_hidden + (size_t)(base + m0 + ar) * D_DIM + k0 + aoff;
            va0 = *(const float4*)(ap);
            va1 = *(const float4*)(ap + 4);
        } else {
            va0 = make_float4(0.f, 0.f, 0.f, 0.f);
            va1 = va0;
        }
        As[aoff + 0][ar] = va0.x; As[aoff + 1][ar] = va0.y;
        As[aoff + 2][ar] = va0.z; As[aoff + 3][ar] = va0.w;
        As[aoff + 4][ar] = va1.x; As[aoff + 5][ar] = va1.y;
        As[aoff + 6][ar] = va1.z; As[aoff + 7][ar] = va1.w;
        float4 vb0 = *(const float4*)(B + (size_t)(k0 + bk0)     * C_DIM + bn);
        float4 vb1 = *(const float4*)(B + (size_t)(k0 + bk0 + 8) * C_DIM + bn);
        *(float4*)&Bs[bk0][bn]     = vb0;
        *(float4*)&Bs[bk0 + 8][bn] = vb1;
        __syncthreads();

#pragma unroll
        for (int kk = 0; kk < 16; kk++) {
            float4 a0 = *(float4*)&As[kk][ty * 8];
            float4 a1 = *(float4*)&As[kk][ty * 8 + 4];
            float4 b0 = *(float4*)&Bs[kk][tx * 8];
            float4 b1 = *(float4*)&Bs[kk][tx * 8 + 4];
            float a[8] = {a0.x, a0.y, a0.z, a0.w, a1.x, a1.y, a1.z, a1.w};
            float b[8] = {b0.x, b0.y, b0.z, b0.w, b1.x, b1.y, b1.z, b1.w};
#pragma unroll
            for (int i = 0; i < 8; i++)
#pragma unroll
                for (int j = 0; j < 8; j++) acc[i][j] += a[i] * b[j];
        }
        __syncthreads();
    }

    // epilogue: scale by prob, atomic-accumulate into out
#pragma unroll
    for (int i = 0; i < 8; i++) {
        int mrow = ty * 8 + i;
        int m = m0 + mrow;
        if (m >= ne) break;
        int token = stok[mrow];
        float p   = sp[mrow];
        float* op = out + (size_t)token * C_DIM + n0 + tx * 8;
#pragma unroll
        for (int j = 0; j < 8; j++)
            atomicAdd(op + j, p * acc[i][j]);
    }
}

// ------------------------------------------------------------------
extern "C" void kernel_launch(void* const* d_in, const int* in_sizes, int n_in,
                              void* d_out, int out_size) {
    const float* x  = (const float*)d_in[0];
    const float* rw = (const float*)d_in[1];
    const float* w1 = (const float*)d_in[2];
    const float* w2 = (const float*)d_in[3];
    float* out = (float*)d_out;

    cudaMemsetAsync(out, 0, (size_t)out_size * sizeof(float));
    init_kernel<<<1, 32>>>();
    router_kernel<<<N_TOK / 8, 256>>>(x, rw);
    offsets_kernel<<<1, 1>>>();
    scatter_kernel<<<N_TOK / 256, 256>>>();

    dim3 g1(D_DIM / 128, 64, E_NUM);
    gemm1_kernel<<<g1, 256>>>(x, w1);
    dim3 g2(C_DIM / 128, 64, E_NUM);
    gemm2_kernel<<<g2, 256>>>(w2, out);
}